// round 9
// baseline (speedup 1.0000x reference)
#include <cuda_runtime.h>
#include <cuda_bf16.h>
#include <cstdint>

#define DIMS        128
#define GAMMA       12.0f
#define MAX_NODES   100000
#define MAX_EDGES   600000
#define SCAN_BLK    1024
#define SCAN_NB     ((MAX_NODES + SCAN_BLK - 1) / SCAN_BLK)   // 98

// ---- device scratch (allocation-free requirement) ------------------------
__device__ int g_counts[MAX_NODES];       // histogram
__device__ int g_cursor[MAX_NODES];       // scatter cursors
__device__ int g_offsets[MAX_NODES + 1];  // CSR offsets
__device__ int g_perm[MAX_EDGES];         // edge ids grouped by dst
__device__ int g_blocksums[SCAN_NB];

// L2 evict-last policy (pin the node table).
__device__ __forceinline__ uint64_t make_evict_last_policy() {
    uint64_t pol;
    asm("createpolicy.fractional.L2::evict_last.b64 %0, 1.0;" : "=l"(pol));
    return pol;
}
__device__ __forceinline__ float4 ldg_pin_l2(const float4* p, uint64_t pol) {
    float4 v;
    asm volatile("ld.global.nc.L2::cache_hint.v4.f32 {%0,%1,%2,%3}, [%4], %5;"
                 : "=f"(v.x), "=f"(v.y), "=f"(v.z), "=f"(v.w)
                 : "l"(p), "l"(pol));
    return v;
}
__device__ __forceinline__ float4 ldg_stream(const float4* p) {
    float4 v;
    asm volatile("ld.global.cs.v4.f32 {%0,%1,%2,%3}, [%4];"
                 : "=f"(v.x), "=f"(v.y), "=f"(v.z), "=f"(v.w)
                 : "l"(p));
    return v;
}
__device__ __forceinline__ void stg_stream(float4* p, float4 v) {
    asm volatile("st.global.cs.v4.f32 [%0], {%1,%2,%3,%4};"
                 :: "l"(p), "f"(v.x), "f"(v.y), "f"(v.z), "f"(v.w)
                 : "memory");
}

// ---- phase 1: build dst-CSR ---------------------------------------------
__global__ void k_zero_counts(int N) {
    int i = blockIdx.x * blockDim.x + threadIdx.x;
    if (i < N) g_counts[i] = 0;
}

__global__ void k_hist(const int* __restrict__ dst, int E) {
    int e = blockIdx.x * blockDim.x + threadIdx.x;
    if (e < E) atomicAdd(&g_counts[dst[e]], 1);
}

// per-block exclusive scan of counts -> offsets, block totals -> blocksums
__global__ void k_scan1(int N) {
    __shared__ int sm[SCAN_BLK];
    int i = blockIdx.x * SCAN_BLK + threadIdx.x;
    int v = (i < N) ? g_counts[i] : 0;
    sm[threadIdx.x] = v;
    __syncthreads();
    for (int off = 1; off < SCAN_BLK; off <<= 1) {
        int t = (threadIdx.x >= off) ? sm[threadIdx.x - off] : 0;
        __syncthreads();
        sm[threadIdx.x] += t;
        __syncthreads();
    }
    if (i < N) g_offsets[i] = sm[threadIdx.x] - v;   // exclusive
    if (threadIdx.x == SCAN_BLK - 1) g_blocksums[blockIdx.x] = sm[threadIdx.x];
}

__global__ void k_scan2() {   // tiny: exclusive scan of 98 block sums
    if (threadIdx.x == 0) {
        int run = 0;
        for (int b = 0; b < SCAN_NB; b++) {
            int t = g_blocksums[b];
            g_blocksums[b] = run;
            run += t;
        }
    }
}

__global__ void k_scan3(int N, int E) {
    int i = blockIdx.x * SCAN_BLK + threadIdx.x;
    if (i < N) {
        int o = g_offsets[i] + g_blocksums[blockIdx.x];
        g_offsets[i] = o;
        g_cursor[i]  = o;
    }
    if (i == 0) g_offsets[N] = E;
}

__global__ void k_scatter(const int* __restrict__ dst, int E) {
    int e = blockIdx.x * blockDim.x + threadIdx.x;
    if (e < E) {
        int pos = atomicAdd(&g_cursor[dst[e]], 1);
        g_perm[pos] = e;
    }
}

// ---- phase 2: one warp per dst node, register accumulation, no atomics ---
__global__ __launch_bounds__(256)
void transe_node_kernel(const float* __restrict__ node_emb,
                        const float* __restrict__ edge_emb,
                        const int*   __restrict__ src,
                        float*       __restrict__ out,
                        int N) {
    const int warp = (blockIdx.x * blockDim.x + threadIdx.x) >> 5;
    const int lane = threadIdx.x & 31;
    if (warp >= N) return;

    const uint64_t pol = make_evict_last_policy();

    const int begin = g_offsets[warp];
    const int end   = g_offsets[warp + 1];

    float4 acc = make_float4(0.f, 0.f, 0.f, 0.f);

    if (begin < end) {
        // tail row loaded ONCE per node
        const float4 t = ldg_pin_l2(
            reinterpret_cast<const float4*>(node_emb + (size_t)warp * DIMS) + lane, pol);

        int e = begin;
        // two-edge unroll for MLP
        for (; e + 1 < end; e += 2) {
            const int e0 = __ldg(g_perm + e);
            const int e1 = __ldg(g_perm + e + 1);
            const int s0 = __ldg(src + e0);
            const int s1 = __ldg(src + e1);

            const float4 h0 = ldg_pin_l2(
                reinterpret_cast<const float4*>(node_emb + (size_t)s0 * DIMS) + lane, pol);
            const float4 r0 = ldg_stream(
                reinterpret_cast<const float4*>(edge_emb + (size_t)e0 * DIMS) + lane);
            const float4 h1 = ldg_pin_l2(
                reinterpret_cast<const float4*>(node_emb + (size_t)s1 * DIMS) + lane, pol);
            const float4 r1 = ldg_stream(
                reinterpret_cast<const float4*>(edge_emb + (size_t)e1 * DIMS) + lane);

            float4 tr0, tr1;
            tr0.x = h0.x + r0.x; tr0.y = h0.y + r0.y;
            tr0.z = h0.z + r0.z; tr0.w = h0.w + r0.w;
            tr1.x = h1.x + r1.x; tr1.y = h1.y + r1.y;
            tr1.z = h1.z + r1.z; tr1.w = h1.w + r1.w;

            float dx, dy, dz, dw;
            dx = tr0.x - t.x; dy = tr0.y - t.y; dz = tr0.z - t.z; dw = tr0.w - t.w;
            float ss0 = dx * dx + dy * dy + dz * dz + dw * dw;
            dx = tr1.x - t.x; dy = tr1.y - t.y; dz = tr1.z - t.z; dw = tr1.w - t.w;
            float ss1 = dx * dx + dy * dy + dz * dz + dw * dw;

            #pragma unroll
            for (int off = 16; off > 0; off >>= 1) {
                ss0 += __shfl_xor_sync(0xffffffffu, ss0, off);
                ss1 += __shfl_xor_sync(0xffffffffu, ss1, off);
            }

            const float sc0 = 1.0f / (1.0f + __expf(sqrtf(ss0) - GAMMA));
            const float sc1 = 1.0f / (1.0f + __expf(sqrtf(ss1) - GAMMA));

            acc.x += sc0 * tr0.x + sc1 * tr1.x;
            acc.y += sc0 * tr0.y + sc1 * tr1.y;
            acc.z += sc0 * tr0.z + sc1 * tr1.z;
            acc.w += sc0 * tr0.w + sc1 * tr1.w;
        }
        if (e < end) {
            const int e0 = __ldg(g_perm + e);
            const int s0 = __ldg(src + e0);
            const float4 h0 = ldg_pin_l2(
                reinterpret_cast<const float4*>(node_emb + (size_t)s0 * DIMS) + lane, pol);
            const float4 r0 = ldg_stream(
                reinterpret_cast<const float4*>(edge_emb + (size_t)e0 * DIMS) + lane);

            float4 tr0;
            tr0.x = h0.x + r0.x; tr0.y = h0.y + r0.y;
            tr0.z = h0.z + r0.z; tr0.w = h0.w + r0.w;

            float dx = tr0.x - t.x, dy = tr0.y - t.y;
            float dz = tr0.z - t.z, dw = tr0.w - t.w;
            float ss0 = dx * dx + dy * dy + dz * dz + dw * dw;
            #pragma unroll
            for (int off = 16; off > 0; off >>= 1)
                ss0 += __shfl_xor_sync(0xffffffffu, ss0, off);

            const float sc0 = 1.0f / (1.0f + __expf(sqrtf(ss0) - GAMMA));
            acc.x += sc0 * tr0.x; acc.y += sc0 * tr0.y;
            acc.z += sc0 * tr0.z; acc.w += sc0 * tr0.w;
        }
    }

    // each output row written exactly once -> streaming store, no zero-init
    stg_stream(reinterpret_cast<float4*>(out + (size_t)warp * DIMS) + lane, acc);
}

// -------------------------------------------------------------------------
// Harness entry. Inputs (metadata order):
//   d_in[0] node_emb  float32 [N,128]
//   d_in[1] edge_emb  float32 [E,128]
//   d_in[2] src       int32   [E]
//   d_in[3] dst       int32   [E]
// d_out: float32 [N,128]
// -------------------------------------------------------------------------
extern "C" void kernel_launch(void* const* d_in, const int* in_sizes, int n_in,
                              void* d_out, int out_size) {
    const float* node_emb = (const float*)d_in[0];
    const float* edge_emb = (const float*)d_in[1];
    const int*   src      = (const int*)d_in[2];
    const int*   dst      = (const int*)d_in[3];
    float*       out      = (float*)d_out;

    const int E = in_sizes[2];
    const int N = out_size / DIMS;

    const int TB = 256;
    const int nbN = (N + TB - 1) / TB;
    const int nbE = (E + TB - 1) / TB;

    k_zero_counts<<<nbN, TB>>>(N);
    k_hist<<<nbE, TB>>>(dst, E);
    k_scan1<<<(N + SCAN_BLK - 1) / SCAN_BLK, SCAN_BLK>>>(N);
    k_scan2<<<1, 32>>>();
    k_scan3<<<(N + SCAN_BLK - 1) / SCAN_BLK, SCAN_BLK>>>(N, E);
    k_scatter<<<nbE, TB>>>(dst, E);

    // one warp per node
    const int warpsPerBlock = TB / 32;
    const int nbMain = (N + warpsPerBlock - 1) / warpsPerBlock;
    transe_node_kernel<<<nbMain, TB>>>(node_emb, edge_emb, src, out, N);
}

// round 10
// speedup vs baseline: 1.0360x; 1.0360x over previous
#include <cuda_runtime.h>
#include <cuda_bf16.h>
#include <cstdint>

#define DIMS        128
#define GAMMA       12.0f
#define MAX_NODES   100000
#define MAX_EDGES   600000
#define SCAN_BLK    1024
#define SCAN_NB     ((MAX_NODES + SCAN_BLK - 1) / SCAN_BLK)   // 98

// ---- device scratch (allocation-free requirement) ------------------------
__device__ int  g_counts[MAX_NODES];       // histogram
__device__ int  g_cursor[MAX_NODES];       // scatter cursors
__device__ int  g_offsets[MAX_NODES + 1];  // CSR offsets
__device__ int2 g_edge[MAX_EDGES];         // (edge_id, src_id) grouped by dst
__device__ int  g_blocksums[SCAN_NB];

// L2 evict-last policy (pin the node table).
__device__ __forceinline__ uint64_t make_evict_last_policy() {
    uint64_t pol;
    asm("createpolicy.fractional.L2::evict_last.b64 %0, 1.0;" : "=l"(pol));
    return pol;
}
__device__ __forceinline__ float4 ldg_pin_l2(const float4* p, uint64_t pol) {
    float4 v;
    asm volatile("ld.global.nc.L2::cache_hint.v4.f32 {%0,%1,%2,%3}, [%4], %5;"
                 : "=f"(v.x), "=f"(v.y), "=f"(v.z), "=f"(v.w)
                 : "l"(p), "l"(pol));
    return v;
}
__device__ __forceinline__ float4 ldg_stream(const float4* p) {
    float4 v;
    asm volatile("ld.global.cs.v4.f32 {%0,%1,%2,%3}, [%4];"
                 : "=f"(v.x), "=f"(v.y), "=f"(v.z), "=f"(v.w)
                 : "l"(p));
    return v;
}
__device__ __forceinline__ void stg_stream(float4* p, float4 v) {
    asm volatile("st.global.cs.v4.f32 [%0], {%1,%2,%3,%4};"
                 :: "l"(p), "f"(v.x), "f"(v.y), "f"(v.z), "f"(v.w)
                 : "memory");
}

// ---- phase 1: build dst-CSR ---------------------------------------------
__global__ void k_zero_counts(int N) {
    int i = blockIdx.x * blockDim.x + threadIdx.x;
    if (i < N) g_counts[i] = 0;
}

__global__ void k_hist(const int* __restrict__ dst, int E) {
    int e = blockIdx.x * blockDim.x + threadIdx.x;
    if (e < E) atomicAdd(&g_counts[dst[e]], 1);
}

// per-block inclusive scan of counts; exclusive result -> offsets,
// block totals -> blocksums
__global__ void k_scan1(int N) {
    __shared__ int sm[SCAN_BLK];
    int i = blockIdx.x * SCAN_BLK + threadIdx.x;
    int v = (i < N) ? g_counts[i] : 0;
    sm[threadIdx.x] = v;
    __syncthreads();
    for (int off = 1; off < SCAN_BLK; off <<= 1) {
        int t = (threadIdx.x >= off) ? sm[threadIdx.x - off] : 0;
        __syncthreads();
        sm[threadIdx.x] += t;
        __syncthreads();
    }
    if (i < N) g_offsets[i] = sm[threadIdx.x] - v;   // exclusive
    if (threadIdx.x == SCAN_BLK - 1) g_blocksums[blockIdx.x] = sm[threadIdx.x];
}

// parallel exclusive scan of the 98 block sums (one 128-thread block)
__global__ void k_scan2() {
    __shared__ int sm[128];
    const int i = threadIdx.x;
    int v = (i < SCAN_NB) ? g_blocksums[i] : 0;
    sm[i] = v;
    __syncthreads();
    #pragma unroll
    for (int off = 1; off < 128; off <<= 1) {
        int t = (i >= off) ? sm[i - off] : 0;
        __syncthreads();
        sm[i] += t;
        __syncthreads();
    }
    if (i < SCAN_NB) g_blocksums[i] = sm[i] - v;     // exclusive
}

__global__ void k_scan3(int N, int E) {
    int i = blockIdx.x * SCAN_BLK + threadIdx.x;
    if (i < N) {
        int o = g_offsets[i] + g_blocksums[blockIdx.x];
        g_offsets[i] = o;
        g_cursor[i]  = o;
    }
    if (i == 0) g_offsets[N] = E;
}

// scatter packed (edge_id, src_id) so the main loop has ONE index load
// per edge instead of a perm->src dependent chain.
__global__ void k_scatter(const int* __restrict__ dst,
                          const int* __restrict__ src, int E) {
    int e = blockIdx.x * blockDim.x + threadIdx.x;
    if (e < E) {
        int pos = atomicAdd(&g_cursor[dst[e]], 1);
        g_edge[pos] = make_int2(e, src[e]);
    }
}

// ---- phase 2: one warp per dst node, register accumulation, no atomics ---
__global__ __launch_bounds__(256)
void transe_node_kernel(const float* __restrict__ node_emb,
                        const float* __restrict__ edge_emb,
                        float*       __restrict__ out,
                        int N) {
    const int warp = (blockIdx.x * blockDim.x + threadIdx.x) >> 5;
    const int lane = threadIdx.x & 31;
    if (warp >= N) return;

    const uint64_t pol = make_evict_last_policy();

    const int begin = g_offsets[warp];
    const int end   = g_offsets[warp + 1];

    float4 acc = make_float4(0.f, 0.f, 0.f, 0.f);

    if (begin < end) {
        // tail row loaded ONCE per node
        const float4 t = ldg_pin_l2(
            reinterpret_cast<const float4*>(node_emb + (size_t)warp * DIMS) + lane, pol);

        int e = begin;
        for (; e + 1 < end; e += 2) {
            const int2 ed0 = __ldg(g_edge + e);
            const int2 ed1 = __ldg(g_edge + e + 1);

            const float4 h0 = ldg_pin_l2(
                reinterpret_cast<const float4*>(node_emb + (size_t)ed0.y * DIMS) + lane, pol);
            const float4 r0 = ldg_stream(
                reinterpret_cast<const float4*>(edge_emb + (size_t)ed0.x * DIMS) + lane);
            const float4 h1 = ldg_pin_l2(
                reinterpret_cast<const float4*>(node_emb + (size_t)ed1.y * DIMS) + lane, pol);
            const float4 r1 = ldg_stream(
                reinterpret_cast<const float4*>(edge_emb + (size_t)ed1.x * DIMS) + lane);

            float4 tr0, tr1;
            tr0.x = h0.x + r0.x; tr0.y = h0.y + r0.y;
            tr0.z = h0.z + r0.z; tr0.w = h0.w + r0.w;
            tr1.x = h1.x + r1.x; tr1.y = h1.y + r1.y;
            tr1.z = h1.z + r1.z; tr1.w = h1.w + r1.w;

            float dx, dy, dz, dw;
            dx = tr0.x - t.x; dy = tr0.y - t.y; dz = tr0.z - t.z; dw = tr0.w - t.w;
            float ss0 = dx * dx + dy * dy + dz * dz + dw * dw;
            dx = tr1.x - t.x; dy = tr1.y - t.y; dz = tr1.z - t.z; dw = tr1.w - t.w;
            float ss1 = dx * dx + dy * dy + dz * dz + dw * dw;

            #pragma unroll
            for (int off = 16; off > 0; off >>= 1) {
                ss0 += __shfl_xor_sync(0xffffffffu, ss0, off);
                ss1 += __shfl_xor_sync(0xffffffffu, ss1, off);
            }

            const float sc0 = 1.0f / (1.0f + __expf(sqrtf(ss0) - GAMMA));
            const float sc1 = 1.0f / (1.0f + __expf(sqrtf(ss1) - GAMMA));

            acc.x += sc0 * tr0.x + sc1 * tr1.x;
            acc.y += sc0 * tr0.y + sc1 * tr1.y;
            acc.z += sc0 * tr0.z + sc1 * tr1.z;
            acc.w += sc0 * tr0.w + sc1 * tr1.w;
        }
        if (e < end) {
            const int2 ed0 = __ldg(g_edge + e);
            const float4 h0 = ldg_pin_l2(
                reinterpret_cast<const float4*>(node_emb + (size_t)ed0.y * DIMS) + lane, pol);
            const float4 r0 = ldg_stream(
                reinterpret_cast<const float4*>(edge_emb + (size_t)ed0.x * DIMS) + lane);

            float4 tr0;
            tr0.x = h0.x + r0.x; tr0.y = h0.y + r0.y;
            tr0.z = h0.z + r0.z; tr0.w = h0.w + r0.w;

            float dx = tr0.x - t.x, dy = tr0.y - t.y;
            float dz = tr0.z - t.z, dw = tr0.w - t.w;
            float ss0 = dx * dx + dy * dy + dz * dz + dw * dw;
            #pragma unroll
            for (int off = 16; off > 0; off >>= 1)
                ss0 += __shfl_xor_sync(0xffffffffu, ss0, off);

            const float sc0 = 1.0f / (1.0f + __expf(sqrtf(ss0) - GAMMA));
            acc.x += sc0 * tr0.x; acc.y += sc0 * tr0.y;
            acc.z += sc0 * tr0.z; acc.w += sc0 * tr0.w;
        }
    }

    // each output row written exactly once -> streaming store, no zero-init
    stg_stream(reinterpret_cast<float4*>(out + (size_t)warp * DIMS) + lane, acc);
}

// -------------------------------------------------------------------------
// Harness entry. Inputs (metadata order):
//   d_in[0] node_emb  float32 [N,128]
//   d_in[1] edge_emb  float32 [E,128]
//   d_in[2] src       int32   [E]
//   d_in[3] dst       int32   [E]
// d_out: float32 [N,128]
// -------------------------------------------------------------------------
extern "C" void kernel_launch(void* const* d_in, const int* in_sizes, int n_in,
                              void* d_out, int out_size) {
    const float* node_emb = (const float*)d_in[0];
    const float* edge_emb = (const float*)d_in[1];
    const int*   src      = (const int*)d_in[2];
    const int*   dst      = (const int*)d_in[3];
    float*       out      = (float*)d_out;

    const int E = in_sizes[2];
    const int N = out_size / DIMS;

    const int TB = 256;
    const int nbN = (N + TB - 1) / TB;
    const int nbE = (E + TB - 1) / TB;

    k_zero_counts<<<nbN, TB>>>(N);
    k_hist<<<nbE, TB>>>(dst, E);
    k_scan1<<<(N + SCAN_BLK - 1) / SCAN_BLK, SCAN_BLK>>>(N);
    k_scan2<<<1, 128>>>();
    k_scan3<<<(N + SCAN_BLK - 1) / SCAN_BLK, SCAN_BLK>>>(N, E);
    k_scatter<<<nbE, TB>>>(dst, src, E);

    // one warp per node
    const int warpsPerBlock = TB / 32;
    const int nbMain = (N + warpsPerBlock - 1) / warpsPerBlock;
    transe_node_kernel<<<nbMain, TB>>>(node_emb, edge_emb, out, N);
}